// round 12
// baseline (speedup 1.0000x reference)
#include <cuda_runtime.h>
#include <cuda_fp16.h>
#include <cstdint>
#include <cstddef>

#define SEQ 65536
#define HID 128
#define NG  512
#define INP 64

// x-gate scratch, split layout (+2 steps padding for prefetch):
//   j <  64: slot = (j>>4)*64 + (gate*8 + (j&7))*2 + ((j>>3)&1)   [scalar half]
//   j >= 64: slot = 256 + (j-64)*4 + gate                          [HMMA half]
static __device__ float g_xg[(size_t)(SEQ + 2) * NG];

union F2U { float2 f; unsigned long long u; };
union H4U { float4 v; __half2 h[4]; };

static __device__ __forceinline__ unsigned long long ld2(const float2* p) {
    F2U u; u.f = *p; return u.u;
}
static __device__ __forceinline__ unsigned long long ffma2(unsigned long long a,
                                                           unsigned long long b,
                                                           unsigned long long c) {
    unsigned long long d;
    asm("fma.rn.f32x2 %0, %1, %2, %3;" : "=l"(d) : "l"(a), "l"(b), "l"(c));
    return d;
}
static __device__ __forceinline__ unsigned long long fadd2(unsigned long long a,
                                                           unsigned long long b) {
    unsigned long long d;
    asm("add.rn.f32x2 %0, %1, %2;" : "=l"(d) : "l"(a), "l"(b));
    return d;
}
static __device__ __forceinline__ float hsum2(unsigned long long a) {
    F2U u; u.u = a; return u.f.x + u.f.y;
}
static __device__ __forceinline__ float ftanh(float x) {
    float y; asm("tanh.approx.f32 %0, %1;" : "=f"(y) : "f"(x)); return y;
}
static __device__ __forceinline__ float fsigm(float x) {
    return fmaf(0.5f, ftanh(0.5f * x), 0.5f);
}

#define MMA(d0, d1, d2, d3, a0, a1, a2, a3, b0, b1)                            \
    asm volatile(                                                              \
        "mma.sync.aligned.m16n8k16.row.col.f32.f16.f16.f32 "                   \
        "{%0,%1,%2,%3}, {%4,%5,%6,%7}, {%8,%9}, {%0,%1,%2,%3};"                \
        : "+f"(d0), "+f"(d1), "+f"(d2), "+f"(d3)                               \
        : "r"(a0), "r"(a1), "r"(a2), "r"(a3), "r"(b0), "r"(b1))

// ---------------------------------------------------------------------------
// Phase 1: x_gates with the split layout above.
// ---------------------------------------------------------------------------
__global__ void __launch_bounds__(512, 1)
gemm_xg(const float* __restrict__ x, const float* __restrict__ Wih,
        const float* __restrict__ bih, const float* __restrict__ bhh)
{
    __shared__ __align__(16) float xs[128 * INP];
    const int r  = threadIdx.x;
    const int t0 = blockIdx.x * 128;

    {
        const float4* src = (const float4*)(x + (size_t)t0 * INP);
        float4* dst = (float4*)xs;
        #pragma unroll
        for (int i = r; i < 128 * INP / 4; i += 512) dst[i] = src[i];
    }

    unsigned long long w[32];
    {
        const float2* wr = (const float2*)(Wih + (size_t)r * INP);
        #pragma unroll
        for (int i = 0; i < 32; i++) w[i] = ld2(wr + i);
    }
    const float bias = bih[r] + bhh[r];

    const int gate = r >> 7, j = r & 127;
    int slot;
    if (j < 64) {
        const int wq = j >> 4, jj = j & 15, hb = jj >> 3, js = jj & 7;
        slot = wq * 64 + (gate * 8 + js) * 2 + hb;
    } else {
        slot = 256 + (j - 64) * 4 + gate;
    }
    __syncthreads();

    for (int tt = 0; tt < 128; tt++) {
        const float2* xp = (const float2*)(xs + tt * INP);
        unsigned long long a0 = 0ull, a1 = 0ull, a2 = 0ull, a3 = 0ull;
        #pragma unroll
        for (int i = 0; i < 32; i += 4) {
            a0 = ffma2(w[i + 0], ld2(xp + i + 0), a0);
            a1 = ffma2(w[i + 1], ld2(xp + i + 1), a1);
            a2 = ffma2(w[i + 2], ld2(xp + i + 2), a2);
            a3 = ffma2(w[i + 3], ld2(xp + i + 3), a3);
        }
        g_xg[(size_t)(t0 + tt) * NG + slot] =
            hsum2(fadd2(fadd2(a0, a1), fadd2(a2, a3))) + bias;
    }
}

// ---------------------------------------------------------------------------
// Phase 2+3: single-CTA hybrid scan, 256 threads.
//   Warps 0-3 (scalar/HFMA2): columns j in [0,64). Warp w: jA=w*16+jsub,
//     jB=jA+8; 2 full W_hh rows per thread in wreg (R10 structure).
//   Warps 4-7 (HMMA): columns j in [64,128). Warp w-4 owns 16 columns,
//     4 gate M-tiles; fragments in wreg (R11 structure).
// Both paths share one wreg[128] (half2) array -> no register blowup.
// One __syncthreads per step at a common point.
// ---------------------------------------------------------------------------
__global__ void __launch_bounds__(256, 1)
lstm_scan(const float* __restrict__ Whh,
          const float* __restrict__ Wlin,
          const float* __restrict__ blin,
          float* __restrict__ out)
{
    __shared__ __align__(16) __half h_s[2][HID];

    const int tid  = threadIdx.x;
    const int w_id = tid >> 5;
    const int lane = tid & 31;
    const bool is_scalar = (w_id < 4);

    __half2 wreg[128];

    // scalar-path ids
    const int gate = lane >> 3;
    const int jsub = lane & 7;
    const int jA   = w_id * 16 + jsub;          // valid if is_scalar
    // hmma-path ids
    const int r0 = lane >> 2;                    // row-in-tile 0..7
    const int kq = lane & 3;
    const int jb = 64 + (w_id - 4) * 16;         // valid if !is_scalar
    const bool act = (kq == 0);

    if (is_scalar) {
        const float2* pa = (const float2*)(Whh + (size_t)(gate * HID + jA) * HID);
        const float2* pb = (const float2*)(Whh + (size_t)(gate * HID + jA + 8) * HID);
        #pragma unroll
        for (int i = 0; i < 64; i++) wreg[i]      = __float22half2_rn(pa[i]);
        #pragma unroll
        for (int i = 0; i < 64; i++) wreg[64 + i] = __float22half2_rn(pb[i]);
    } else {
        #pragma unroll
        for (int g = 0; g < 4; g++) {
            const float* rA = Whh + (size_t)(g * HID + jb + r0) * HID;
            const float* rB = Whh + (size_t)(g * HID + jb + r0 + 8) * HID;
            #pragma unroll
            for (int kk = 0; kk < 8; kk++) {
                const int c0 = kk * 16 + 2 * kq;
                wreg[g * 32 + kk * 4 + 0] = __float22half2_rn(*(const float2*)(rA + c0));
                wreg[g * 32 + kk * 4 + 1] = __float22half2_rn(*(const float2*)(rB + c0));
                wreg[g * 32 + kk * 4 + 2] = __float22half2_rn(*(const float2*)(rA + c0 + 8));
                wreg[g * 32 + kk * 4 + 3] = __float22half2_rn(*(const float2*)(rB + c0 + 8));
            }
        }
    }

    if (tid < 2 * HID) ((__half*)h_s)[tid] = __float2half_rn(0.0f);

    // scalar activation constants
    const float kk_ = (gate == 2) ? 1.0f : 0.5f;
    const float aa_ = (gate == 2) ? 1.0f : 0.5f;
    const float bb_ = (gate == 2) ? 0.0f : 0.5f;

    float cA = 0.0f, cB = 0.0f;
    // scalar xg stream (float2 = {xgA, xgB} for this (gate, jsub))
    const float2* xq = (const float2*)g_xg + w_id * 32 + gate * 8 + jsub;
    // hmma xg stream (float4 = 4 gates of one column)
    const float4* xb = (const float4*)g_xg + 64 + (w_id - 4) * 16 + r0;

    float2 xcur[2];
    float4 xA[2], xB[2];
    if (is_scalar) {
        xcur[0] = xq[0];
        xcur[1] = xq[NG / 2];
    } else if (act) {
        xA[0] = xb[0];          xB[0] = xb[8];
        xA[1] = xb[NG / 4];     xB[1] = xb[NG / 4 + 8];
    }

    __syncthreads();

#define STEP(B)                                                                \
    {                                                                          \
        if (is_scalar) {                                                       \
            const float4* hp = (const float4*)h_s[(B) ^ 1];                    \
            __half2 z = __float2half2_rn(0.0f);                                \
            __half2 aA0 = z, aA1 = z, aA2 = z, aA3 = z;                        \
            __half2 aB0 = z, aB1 = z, aB2 = z, aB3 = z;                        \
            _Pragma("unroll")                                                  \
            for (int i = 0; i < 16; i++) {                                     \
                H4U q; q.v = hp[i];                                            \
                aA0 = __hfma2(wreg[4 * i + 0], q.h[0], aA0);                   \
                aA1 = __hfma2(wreg[4 * i + 1], q.h[1], aA1);                   \
                aA2 = __hfma2(wreg[4 * i + 2], q.h[2], aA2);                   \
                aA3 = __hfma2(wreg[4 * i + 3], q.h[3], aA3);                   \
                aB0 = __hfma2(wreg[64 + 4 * i + 0], q.h[0], aB0);              \
                aB1 = __hfma2(wreg[64 + 4 * i + 1], q.h[1], aB1);              \
                aB2 = __hfma2(wreg[64 + 4 * i + 2], q.h[2], aB2);              \
                aB3 = __hfma2(wreg[64 + 4 * i + 3], q.h[3], aB3);              \
            }                                                                  \
            aA0 = __hadd2(aA0, aA1); aA2 = __hadd2(aA2, aA3);                  \
            aB0 = __hadd2(aB0, aB1); aB2 = __hadd2(aB2, aB3);                  \
            aA0 = __hadd2(aA0, aA2);                                           \
            aB0 = __hadd2(aB0, aB2);                                           \
            const float sA = xcur[B].x + __low2float(aA0) + __high2float(aA0); \
            const float sB = xcur[B].y + __low2float(aB0) + __high2float(aB0); \
            xcur[B] = xq[NG];                                                  \
            xq += NG / 2;                                                      \
            const float yA = fmaf(aa_, ftanh(kk_ * sA), bb_);                  \
            const float yB = fmaf(aa_, ftanh(kk_ * sB), bb_);                  \
            const float ivA = __shfl_sync(0xffffffffu, yA, jsub);              \
            const float fvA = __shfl_sync(0xffffffffu, yA, jsub + 8);          \
            const float gvA = __shfl_sync(0xffffffffu, yA, jsub + 16);         \
            const float ovA = __shfl_sync(0xffffffffu, yA, jsub + 24);         \
            const float ivB = __shfl_sync(0xffffffffu, yB, jsub);              \
            const float fvB = __shfl_sync(0xffffffffu, yB, jsub + 8);          \
            const float gvB = __shfl_sync(0xffffffffu, yB, jsub + 16);         \
            const float ovB = __shfl_sync(0xffffffffu, yB, jsub + 24);         \
            cA = fmaf(fvA, cA, ivA * gvA);                                     \
            cB = fmaf(fvB, cB, ivB * gvB);                                     \
            const float hvA = ovA * ftanh(cA);                                 \
            const float hvB = ovB * ftanh(cB);                                 \
            if (lane < 8) {                                                    \
                h_s[B][w_id * 16 + lane]     = __float2half_rn(hvA);           \
                h_s[B][w_id * 16 + 8 + lane] = __float2half_rn(hvB);           \
            }                                                                  \
        } else {                                                               \
            const __half* hs = h_s[(B) ^ 1];                                   \
            float d[4][4];                                                     \
            _Pragma("unroll")                                                  \
            for (int g = 0; g < 4; g++) {                                      \
                d[g][0] = 0.0f; d[g][1] = 0.0f;                                \
                d[g][2] = 0.0f; d[g][3] = 0.0f;                                \
            }                                                                  \
            _Pragma("unroll")                                                  \
            for (int kk = 0; kk < 8; kk++) {                                   \
                uint32_t b01 = 0u, b23 = 0u;                                   \
                if (lane < 4) {                                                \
                    b01 = *(const uint32_t*)(hs + kk * 16 + 2 * lane);         \
                    b23 = *(const uint32_t*)(hs + kk * 16 + 2 * lane + 8);     \
                }                                                              \
                _Pragma("unroll")                                              \
                for (int g = 0; g < 4; g++) {                                  \
                    MMA(d[g][0], d[g][1], d[g][2], d[g][3],                    \
                        *(const uint32_t*)&wreg[g * 32 + kk * 4 + 0],          \
                        *(const uint32_t*)&wreg[g * 32 + kk * 4 + 1],          \
                        *(const uint32_t*)&wreg[g * 32 + kk * 4 + 2],          \
                        *(const uint32_t*)&wreg[g * 32 + kk * 4 + 3],          \
                        b01, b23);                                             \
                }                                                              \
            }                                                                  \
            if (act) {                                                         \
                const float iA = fsigm(d[0][0] + xA[B].x);                     \
                const float fA = fsigm(d[1][0] + xA[B].y);                     \
                const float gA = ftanh(d[2][0] + xA[B].z);                     \
                const float oA = fsigm(d[3][0] + xA[B].w);                     \
                const float iB = fsigm(d[0][2] + xB[B].x);                     \
                const float fB = fsigm(d[1][2] + xB[B].y);                     \
                const float gB = ftanh(d[2][2] + xB[B].z);                     \
                const float oB = fsigm(d[3][2] + xB[B].w);                     \
                cA = fmaf(fA, cA, iA * gA);                                    \
                cB = fmaf(fB, cB, iB * gB);                                    \
                h_s[B][jb + r0]     = __float2half_rn(oA * ftanh(cA));         \
                h_s[B][jb + r0 + 8] = __float2half_rn(oB * ftanh(cB));         \
                xA[B] = xb[2 * (NG / 4)];                                      \
                xB[B] = xb[2 * (NG / 4) + 8];                                  \
                xb += NG / 4;                                                  \
            }                                                                  \
        }                                                                      \
        __syncthreads();                                                       \
    }

    for (int t = 0; t < SEQ; t += 2) {
        STEP(0)
        STEP(1)
    }

    // h_T in h_s[1]; warp 0 reduces the linear head.
    if (tid < 32) {
        float s = 0.0f;
        #pragma unroll
        for (int m = 0; m < 4; m++)
            s += __half2float(h_s[1][lane + 32 * m]) * Wlin[lane + 32 * m];
        #pragma unroll
        for (int dd = 16; dd > 0; dd >>= 1)
            s += __shfl_xor_sync(0xffffffffu, s, dd);
        if (lane == 0)
            out[0] = fsigm(s + blin[0]);
    }
}

extern "C" void kernel_launch(void* const* d_in, const int* in_sizes, int n_in,
                              void* d_out, int out_size) {
    const float* input = (const float*)d_in[0];
    const float* Wih   = (const float*)d_in[1];
    const float* Whh   = (const float*)d_in[2];
    const float* bih   = (const float*)d_in[3];
    const float* bhh   = (const float*)d_in[4];
    const float* Wlin  = (const float*)d_in[5];
    const float* blin  = (const float*)d_in[6];
    float* out = (float*)d_out;

    gemm_xg<<<SEQ / 128, 512>>>(input, Wih, bih, bhh);
    lstm_scan<<<1, 256>>>(Whh, Wlin, blin, out);
}

// round 13
// speedup vs baseline: 1.3717x; 1.3717x over previous
#include <cuda_runtime.h>
#include <cuda_fp16.h>
#include <cstdint>
#include <cstddef>

#define SEQ 65536
#define HID 128
#define NG  512
#define INP 64

// x-gate scratch, slot = j*4 + gate (+2 steps padding for prefetch)
static __device__ float g_xg[(size_t)(SEQ + 2) * NG];

union F2U { float2 f; unsigned long long u; };
union H4U { float4 v; __half2 h[4]; };

static __device__ __forceinline__ unsigned long long ld2(const float2* p) {
    F2U u; u.f = *p; return u.u;
}
static __device__ __forceinline__ unsigned long long ffma2(unsigned long long a,
                                                           unsigned long long b,
                                                           unsigned long long c) {
    unsigned long long d;
    asm("fma.rn.f32x2 %0, %1, %2, %3;" : "=l"(d) : "l"(a), "l"(b), "l"(c));
    return d;
}
static __device__ __forceinline__ unsigned long long fadd2(unsigned long long a,
                                                           unsigned long long b) {
    unsigned long long d;
    asm("add.rn.f32x2 %0, %1, %2;" : "=l"(d) : "l"(a), "l"(b));
    return d;
}
static __device__ __forceinline__ float hsum2(unsigned long long a) {
    F2U u; u.u = a; return u.f.x + u.f.y;
}
static __device__ __forceinline__ float ftanh(float x) {
    float y; asm("tanh.approx.f32 %0, %1;" : "=f"(y) : "f"(x)); return y;
}
static __device__ __forceinline__ float fsigm(float x) {
    return fmaf(0.5f, ftanh(0.5f * x), 0.5f);
}

// ---------------------------------------------------------------------------
// Phase 1: x_gates with slot = j*4 + gate  (row r = gate*128 + j)
// ---------------------------------------------------------------------------
__global__ void __launch_bounds__(512, 1)
gemm_xg(const float* __restrict__ x, const float* __restrict__ Wih,
        const float* __restrict__ bih, const float* __restrict__ bhh)
{
    __shared__ __align__(16) float xs[128 * INP];
    const int r  = threadIdx.x;
    const int t0 = blockIdx.x * 128;

    {
        const float4* src = (const float4*)(x + (size_t)t0 * INP);
        float4* dst = (float4*)xs;
        #pragma unroll
        for (int i = r; i < 128 * INP / 4; i += 512) dst[i] = src[i];
    }

    unsigned long long w[32];
    {
        const float2* wr = (const float2*)(Wih + (size_t)r * INP);
        #pragma unroll
        for (int i = 0; i < 32; i++) w[i] = ld2(wr + i);
    }
    const float bias = bih[r] + bhh[r];
    const int slot = (r & 127) * 4 + (r >> 7);
    __syncthreads();

    for (int tt = 0; tt < 128; tt++) {
        const float2* xp = (const float2*)(xs + tt * INP);
        unsigned long long a0 = 0ull, a1 = 0ull, a2 = 0ull, a3 = 0ull;
        #pragma unroll
        for (int i = 0; i < 32; i += 4) {
            a0 = ffma2(w[i + 0], ld2(xp + i + 0), a0);
            a1 = ffma2(w[i + 1], ld2(xp + i + 1), a1);
            a2 = ffma2(w[i + 2], ld2(xp + i + 2), a2);
            a3 = ffma2(w[i + 3], ld2(xp + i + 3), a3);
        }
        g_xg[(size_t)(t0 + tt) * NG + slot] =
            hsum2(fadd2(fadd2(a0, a1), fadd2(a2, a3))) + bias;
    }
}

// ---------------------------------------------------------------------------
// Phase 2+3: single-CTA scan, 256 threads.
// Thread (w, lane): kh = lane>>4, jj = lane&15, column j = w*16 + jj.
// Owns gate rows {g*128+j : g=0..3} restricted to k in [kh*64, kh*64+64):
// 4 x 32 half2 = 128 weight registers. Partial gate sums combined with the
// k-half partner via ONE shfl_xor(16) per gate; both copies then compute
// identical activations and c/h (redundant, divergence-free). kh=0 lanes
// add xg and store h. No gather shuffles at all.
// ---------------------------------------------------------------------------
__global__ void __launch_bounds__(256, 1)
lstm_scan(const float* __restrict__ Whh,
          const float* __restrict__ Wlin,
          const float* __restrict__ blin,
          float* __restrict__ out)
{
    __shared__ __align__(16) __half h_s[2][HID];

    const int tid  = threadIdx.x;
    const int w_id = tid >> 5;
    const int lane = tid & 31;
    const int kh   = lane >> 4;          // k-half 0/1
    const int jj   = lane & 15;
    const int j    = w_id * 16 + jj;     // column 0..127
    const float xmask = (kh == 0) ? 1.0f : 0.0f;

    // Weights: wreg[g][i] covers W_hh[g*128+j][kh*64 + 2i .. +2i+1]
    __half2 wreg[4][32];
    #pragma unroll
    for (int g = 0; g < 4; g++) {
        const float2* wr =
            (const float2*)(Whh + (size_t)(g * HID + j) * HID + kh * 64);
        #pragma unroll
        for (int i = 0; i < 32; i++) wreg[g][i] = __float22half2_rn(wr[i]);
    }

    if (tid < 2 * HID) ((__half*)h_s)[tid] = __float2half_rn(0.0f);

    float c = 0.0f;
    const float4* xb = (const float4*)g_xg + j;   // float4 = 4 gates of col j
    float4 xA[2];
    xA[0] = xb[0];
    xA[1] = xb[NG / 4];

    __syncthreads();

#define STEP(B)                                                                \
    {                                                                          \
        const float4* hp = (const float4*)(h_s[(B) ^ 1] + kh * 64);            \
        __half2 z = __float2half2_rn(0.0f);                                    \
        __half2 a0[4] = {z, z, z, z};                                          \
        __half2 a1[4] = {z, z, z, z};                                          \
        _Pragma("unroll")                                                      \
        for (int i = 0; i < 8; i++) {                                          \
            H4U q; q.v = hp[i];                                                \
            _Pragma("unroll")                                                  \
            for (int g = 0; g < 4; g++) {                                      \
                a0[g] = __hfma2(wreg[g][4 * i + 0], q.h[0], a0[g]);            \
                a1[g] = __hfma2(wreg[g][4 * i + 1], q.h[1], a1[g]);            \
                a0[g] = __hfma2(wreg[g][4 * i + 2], q.h[2], a0[g]);            \
                a1[g] = __hfma2(wreg[g][4 * i + 3], q.h[3], a1[g]);            \
            }                                                                  \
        }                                                                      \
        float part[4];                                                         \
        _Pragma("unroll")                                                      \
        for (int g = 0; g < 4; g++) {                                          \
            const __half2 t = __hadd2(a0[g], a1[g]);                           \
            part[g] = __low2float(t) + __high2float(t);                        \
        }                                                                      \
        part[0] = fmaf(xmask, xA[B].x, part[0]);                               \
        part[1] = fmaf(xmask, xA[B].y, part[1]);                               \
        part[2] = fmaf(xmask, xA[B].z, part[2]);                               \
        part[3] = fmaf(xmask, xA[B].w, part[3]);                               \
        xA[B] = xb[2 * (NG / 4)];                                              \
        xb += NG / 4;                                                          \
        const float s0 = part[0] + __shfl_xor_sync(0xffffffffu, part[0], 16);  \
        const float s1 = part[1] + __shfl_xor_sync(0xffffffffu, part[1], 16);  \
        const float s2 = part[2] + __shfl_xor_sync(0xffffffffu, part[2], 16);  \
        const float s3 = part[3] + __shfl_xor_sync(0xffffffffu, part[3], 16);  \
        const float iv = fsigm(s0);                                            \
        const float fv = fsigm(s1);                                            \
        const float gv = ftanh(s2);                                            \
        const float ov = fsigm(s3);                                            \
        c = fmaf(fv, c, iv * gv);                                              \
        const float hv = ov * ftanh(c);                                        \
        if (kh == 0) h_s[B][j] = __float2half_rn(hv);                          \
        __syncthreads();                                                       \
    }

    for (int t = 0; t < SEQ; t += 2) {
        STEP(0)
        STEP(1)
    }

    // h_T in h_s[1]; warp 0 reduces the linear head.
    if (tid < 32) {
        float s = 0.0f;
        #pragma unroll
        for (int m = 0; m < 4; m++)
            s += __half2float(h_s[1][lane + 32 * m]) * Wlin[lane + 32 * m];
        #pragma unroll
        for (int dd = 16; dd > 0; dd >>= 1)
            s += __shfl_xor_sync(0xffffffffu, s, dd);
        if (lane == 0)
            out[0] = fsigm(s + blin[0]);
    }
}

extern "C" void kernel_launch(void* const* d_in, const int* in_sizes, int n_in,
                              void* d_out, int out_size) {
    const float* input = (const float*)d_in[0];
    const float* Wih   = (const float*)d_in[1];
    const float* Whh   = (const float*)d_in[2];
    const float* bih   = (const float*)d_in[3];
    const float* bhh   = (const float*)d_in[4];
    const float* Wlin  = (const float*)d_in[5];
    const float* blin  = (const float*)d_in[6];
    float* out = (float*)d_out;

    gemm_xg<<<SEQ / 128, 512>>>(input, Wih, bih, bhh);
    lstm_scan<<<1, 256>>>(Whh, Wlin, blin, out);
}